// round 14
// baseline (speedup 1.0000x reference)
#include <cuda_runtime.h>
#include <cuda_fp16.h>
#include <cstdint>

// ---------------------------------------------------------------------------
// Problem shape
#define NB   32      // batch
#define NT   1000    // time steps
#define NO   1024    // n_out
#define NI   1024    // n_in (K)
#define NTP  1024    // padded T

// Scratch (__device__ globals zero-initialized; pad rows stay zero)
__device__ float g_cur[(size_t)NB * NT * NO];             // currents [b][t][o]
__device__ __half g_xh[(size_t)2 * NB * NTP * NI];        // x fp16 planes [p][b][t][k]
__device__ __half g_wh[(size_t)2 * NO * NI];              // w fp16 planes [p][n][k]

__device__ __forceinline__ uint32_t smem_u32(const void* p) {
    uint32_t a;
    asm("{ .reg .u64 t; cvta.to.shared.u64 t, %1; cvt.u32.u64 %0, t; }" : "=r"(a) : "l"(p));
    return a;
}

// fp32 -> 2x fp16 split (11+11 mantissa bits)
__device__ __forceinline__ void split2_f16(float v, __half& h0, __half& h1) {
    h0 = __float2half_rn(v);
    float r = __fsub_rn(v, __half2float(h0));
    h1 = __float2half_rn(r);
}

// ---------------------------------------------------------------------------
// wconv: w[k][n] (f32) -> g_wh[p][n][k] (fp16 planes, transposed)
// ---------------------------------------------------------------------------
__global__ __launch_bounds__(256)
void wconv_kernel(const float* __restrict__ w)
{
    __shared__ float tile[32][33];
    const int k0 = blockIdx.x * 32;
    const int n0 = blockIdx.y * 32;
    const int tx = threadIdx.x, ty = threadIdx.y;   // (32, 8)
#pragma unroll
    for (int j = 0; j < 4; j++) {
        int k = k0 + ty + 8 * j;
        tile[ty + 8 * j][tx] = w[(size_t)k * NO + n0 + tx];
    }
    __syncthreads();
#pragma unroll
    for (int j = 0; j < 4; j++) {
        int r = ty + 8 * j;
        int n = n0 + r;
        __half h0, h1;
        split2_f16(tile[tx][r], h0, h1);
        size_t base = (size_t)n * NI + k0 + tx;
        g_wh[base]                   = h0;
        g_wh[(size_t)NO * NI + base] = h1;
    }
}

// ---------------------------------------------------------------------------
// xconv: x[b][k][t] (f32) -> g_xh[p][b][t][k] (fp16 planes, transposed per b)
// ---------------------------------------------------------------------------
__global__ __launch_bounds__(256)
void xconv_kernel(const float* __restrict__ x)
{
    __shared__ float tile[32][33];
    const int b  = blockIdx.z;
    const int k0 = blockIdx.y * 32;
    const int t0 = blockIdx.x * 32;
    const int tx = threadIdx.x, ty = threadIdx.y;   // (32, 8)
    const float* xb = x + (size_t)b * NI * NT;
#pragma unroll
    for (int j = 0; j < 4; j++) {
        int k = k0 + ty + 8 * j;
        int t = t0 + tx;
        tile[ty + 8 * j][tx] = (t < NT) ? xb[(size_t)k * NT + t] : 0.0f;
    }
    __syncthreads();
    const size_t plane = (size_t)NB * NTP * NI;
#pragma unroll
    for (int j = 0; j < 4; j++) {
        int r = ty + 8 * j;
        int t = t0 + r;
        if (t < NT) {
            __half h0, h1;
            split2_f16(tile[tx][r], h0, h1);
            size_t base = ((size_t)b * NTP + t) * NI + k0 + tx;
            g_xh[base]         = h0;
            g_xh[plane + base] = h1;
        }
    }
}

// ---------------------------------------------------------------------------
// GEMM via mma.sync.m16n8k16.f16, fp32-emulated fp16x3.
// FROZEN numerics (verified rel_err==0.0 in R11): main h0x*h0w -> zero-start
// chunk acc per BK=32 (2 k16 MMAs), folded into master with rn add, chunks
// ascending; corr = h0x*h1w + h1x*h0w chained; final cur = main + corr.
// CTA: 512 thr (16 warps, 4m x 4n), tile 256(t) x 128(o), warp tile 64x32.
// BK=64 smem chunks (two BK=32 folds each), double-buffered cp.async.
// 4 warps/SMSP hide fold/zero/ldsm overhead under tensor-pipe time.
// ---------------------------------------------------------------------------
#define APB    32768             // A plane: 256 rows x 64 fp16 (128B rows)
#define BPB    16384             // B plane: 128 rows x 64 fp16
#define BBASE  (2 * APB)         // B planes start within buffer (65536)
#define BUFB   (2 * APB + 2 * BPB)   // 96 KB
#define SMEMSZ (2 * BUFB)            // 192 KB
#define NC     16                // 1024 / 64 chunks

__device__ __forceinline__ void ldsm4(uint32_t* r, uint32_t addr) {
    asm volatile("ldmatrix.sync.aligned.m8n8.x4.shared.b16 {%0,%1,%2,%3}, [%4];"
        : "=r"(r[0]), "=r"(r[1]), "=r"(r[2]), "=r"(r[3]) : "r"(addr));
}
__device__ __forceinline__ void mma16816(float* d, const uint32_t* a, uint32_t b0, uint32_t b1) {
    asm volatile("mma.sync.aligned.m16n8k16.row.col.f32.f16.f16.f32 "
        "{%0,%1,%2,%3}, {%4,%5,%6,%7}, {%8,%9}, {%0,%1,%2,%3};"
        : "+f"(d[0]), "+f"(d[1]), "+f"(d[2]), "+f"(d[3])
        : "r"(a[0]), "r"(a[1]), "r"(a[2]), "r"(a[3]), "r"(b0), "r"(b1));
}

__device__ __forceinline__ void load_chunk(uint32_t sbuf,
                                           const __half* xb, const __half* wb,
                                           int k0, int tid,
                                           size_t xplane, size_t wplane)
{
    // 6144 16B units: A = 2 planes x 256 rows x 8 ch (0..4095),
    //                 B = 2 planes x 128 rows x 8 ch (4096..6143)
#pragma unroll
    for (int i = 0; i < 12; i++) {
        int v = tid + i * 512;
        uint32_t d;
        const __half* g;
        if (v < 4096) {
            int p   = v >> 11;
            int row = (v >> 3) & 255;
            int ch  = v & 7;
            g = xb + (size_t)p * xplane + (size_t)row * NI + k0 + ch * 8;
            d = sbuf + p * APB + row * 128 + ((ch ^ (row & 7)) * 16);
        } else {
            int v2  = v - 4096;
            int p   = v2 >> 10;
            int row = (v2 >> 3) & 127;
            int ch  = v2 & 7;
            g = wb + (size_t)p * wplane + (size_t)row * NI + k0 + ch * 8;
            d = sbuf + BBASE + p * BPB + row * 128 + ((ch ^ (row & 7)) * 16);
        }
        asm volatile("cp.async.cg.shared.global [%0], [%1], 16;" :: "r"(d), "l"((const void*)g));
    }
}

__global__ __launch_bounds__(512, 1)
void snn_gemm_f16()
{
    extern __shared__ char smem[];
    const int tid  = threadIdx.x;
    const int lane = tid & 31;
    const int wid  = tid >> 5;

    const int b  = blockIdx.z;
    const int t0 = blockIdx.y * 256;
    const int n0 = blockIdx.x * 128;

    const size_t xplane = (size_t)NB * NTP * NI;
    const size_t wplane = (size_t)NO * NI;
    const __half* xb = g_xh + ((size_t)b * NTP + t0) * NI;
    const __half* wb = g_wh + (size_t)n0 * NI;

    const uint32_t sb = smem_u32(smem);

    const int warp_m = (wid >> 2) * 64;    // 0..192
    const int warp_n = (wid & 3) * 32;     // 0..96

    const int rA = (lane & 7) + ((lane >> 3) & 1) * 8;
    const int cA = (lane >> 4) & 1;
    const int rB = (lane & 7) + ((lane >> 4) & 1) * 8;
    const int cB = (lane >> 3) & 1;

    float accM[4][4][4], accC[4][4][4], accH[4][4][4];
#pragma unroll
    for (int mt = 0; mt < 4; mt++)
#pragma unroll
        for (int nt = 0; nt < 4; nt++)
#pragma unroll
            for (int q = 0; q < 4; q++) { accM[mt][nt][q] = 0.f; accC[mt][nt][q] = 0.f; }

    load_chunk(sb, xb, wb, 0, tid, xplane, wplane);
    asm volatile("cp.async.commit_group;" ::: "memory");

    for (int c = 0; c < NC; c++) {
        if (c + 1 < NC) {
            load_chunk(sb + ((c + 1) & 1) * BUFB, xb, wb, (c + 1) * 64, tid, xplane, wplane);
            asm volatile("cp.async.commit_group;" ::: "memory");
            asm volatile("cp.async.wait_group 1;" ::: "memory");
        } else {
            asm volatile("cp.async.wait_group 0;" ::: "memory");
        }
        __syncthreads();

        const uint32_t Ab = sb + (c & 1) * BUFB;
        const uint32_t Bb = Ab + BBASE;

        // Two BK=32 halves per smem chunk; fresh chunk accumulator each half
        // (FROZEN: fold granularity must stay at 32 k-elements)
#pragma unroll
        for (int half = 0; half < 2; half++) {
#pragma unroll
            for (int mt = 0; mt < 4; mt++)
#pragma unroll
                for (int nt = 0; nt < 4; nt++)
#pragma unroll
                    for (int q = 0; q < 4; q++) accH[mt][nt][q] = 0.f;

#pragma unroll
            for (int kss = 0; kss < 2; kss++) {
                const int ks = half * 2 + kss;
                // B fragments: 2 planes x 2 n16-groups
                uint32_t bf[2][2][4];
#pragma unroll
                for (int p = 0; p < 2; p++)
#pragma unroll
                    for (int np = 0; np < 2; np++) {
                        int r  = warp_n + np * 16 + rB;
                        int ch = (ks * 2 + cB) ^ (r & 7);
                        ldsm4(bf[p][np], Bb + p * BPB + r * 128 + ch * 16);
                    }
#pragma unroll
                for (int mt = 0; mt < 4; mt++) {
                    int r  = warp_m + mt * 16 + rA;
                    int ch = (ks * 2 + cA) ^ (r & 7);
                    uint32_t a0f[4], a1f[4];
                    ldsm4(a0f, Ab + r * 128 + ch * 16);          // h0 plane
#pragma unroll
                    for (int nt = 0; nt < 4; nt++) {
                        // main: h0x * h0w -> chunk accumulator
                        mma16816(accH[mt][nt], a0f,
                                 bf[0][nt >> 1][(nt & 1) * 2], bf[0][nt >> 1][(nt & 1) * 2 + 1]);
                        // corr: h0x * h1w
                        mma16816(accC[mt][nt], a0f,
                                 bf[1][nt >> 1][(nt & 1) * 2], bf[1][nt >> 1][(nt & 1) * 2 + 1]);
                    }
                    ldsm4(a1f, Ab + APB + r * 128 + ch * 16);    // h1 plane
#pragma unroll
                    for (int nt = 0; nt < 4; nt++) {
                        // corr: h1x * h0w
                        mma16816(accC[mt][nt], a1f,
                                 bf[0][nt >> 1][(nt & 1) * 2], bf[0][nt >> 1][(nt & 1) * 2 + 1]);
                    }
                }
            }

            // fold BK=32 chunk into master (rn add at full magnitude)
#pragma unroll
            for (int mt = 0; mt < 4; mt++)
#pragma unroll
                for (int nt = 0; nt < 4; nt++)
#pragma unroll
                    for (int q = 0; q < 4; q++)
                        accM[mt][nt][q] = __fadd_rn(accM[mt][nt][q], accH[mt][nt][q]);
        }
        __syncthreads();
    }

    // Epilogue: cur = main + corr
    float* __restrict__ cb = g_cur + (size_t)b * NT * NO;
#pragma unroll
    for (int mt = 0; mt < 4; mt++) {
        int r0 = t0 + warp_m + mt * 16 + (lane >> 2);
#pragma unroll
        for (int nt = 0; nt < 4; nt++) {
            int cc = n0 + warp_n + nt * 8 + (lane & 3) * 2;
            float2 v0, v1;
            v0.x = __fadd_rn(accM[mt][nt][0], accC[mt][nt][0]);
            v0.y = __fadd_rn(accM[mt][nt][1], accC[mt][nt][1]);
            v1.x = __fadd_rn(accM[mt][nt][2], accC[mt][nt][2]);
            v1.y = __fadd_rn(accM[mt][nt][3], accC[mt][nt][3]);
            if (r0 < NT)
                *reinterpret_cast<float2*>(cb + (size_t)r0 * NO + cc) = v0;
            if (r0 + 8 < NT)
                *reinterpret_cast<float2*>(cb + (size_t)(r0 + 8) * NO + cc) = v1;
        }
    }
}

// ---------------------------------------------------------------------------
// Scan: per (b,o) neuron, serial over t (exact reference rounding order).
// ---------------------------------------------------------------------------
#define TT 40   // 1000 % 40 == 0

__global__ __launch_bounds__(128)
void snn_scan_kernel(float* __restrict__ out)
{
    __shared__ float s[128][TT + 1];

    const int b  = blockIdx.y;
    const int o0 = blockIdx.x * 128;
    const int o  = o0 + threadIdx.x;

    const float* __restrict__ cb = g_cur + (size_t)b * NT * NO;
    const float DT = (float)(0.001 / 50.0);

    float v = 0.0f;

    for (int tc = 0; tc < NT; tc += TT) {
#pragma unroll
        for (int tt = 0; tt < TT; tt++) {
            float cur = cb[(size_t)(tc + tt) * NO + o];
            float d  = __fsub_rn(cur, v);
            float dv = __fmul_rn(d, DT);
            v = __fadd_rn(v, dv);
            bool sp = (v >= 1.0f);
            s[threadIdx.x][tt] = sp ? 1.0f : 0.0f;
            v = sp ? 0.0f : v;
        }
        __syncthreads();

        for (int idx = threadIdx.x; idx < 128 * TT; idx += 128) {
            int oo = idx / TT;
            int tt = idx - oo * TT;
            out[((size_t)b * NO + (o0 + oo)) * NT + tc + tt] = s[oo][tt];
        }
        __syncthreads();
    }
}

// ---------------------------------------------------------------------------
extern "C" void kernel_launch(void* const* d_in, const int* in_sizes, int n_in,
                              void* d_out, int out_size)
{
    const float* x = (const float*)d_in[0];   // [32, 1024, 1000]
    const float* w = (const float*)d_in[1];   // [1024, 1024]
    float* out = (float*)d_out;               // [32, 1024, 1000]

    (void)in_sizes; (void)n_in; (void)out_size;

    cudaFuncSetAttribute(snn_gemm_f16, cudaFuncAttributeMaxDynamicSharedMemorySize, SMEMSZ);

    dim3 wgrid(NI / 32, NO / 32);                 // 32 x 32
    wconv_kernel<<<wgrid, dim3(32, 8)>>>(w);

    dim3 xgrid((NT + 31) / 32, NI / 32, NB);      // 32 x 32 x 32
    xconv_kernel<<<xgrid, dim3(32, 8)>>>(x);

    dim3 ggrid(NO / 128, NTP / 256, NB);          // 8 x 4 x 32
    snn_gemm_f16<<<ggrid, 512, SMEMSZ>>>();

    dim3 sgrid(NO / 128, NB);                     // 8 x 32
    snn_scan_kernel<<<sgrid, 128>>>(out);
}

// round 15
// speedup vs baseline: 1.7813x; 1.7813x over previous
#include <cuda_runtime.h>
#include <cuda_fp16.h>
#include <cstdint>

// ---------------------------------------------------------------------------
// Problem shape
#define NB   32      // batch
#define NT   1000    // time steps
#define NO   1024    // n_out
#define NI   1024    // n_in (K)
#define NTP  1024    // padded T

// Scratch (__device__ globals zero-initialized; pad rows stay zero)
__device__ float g_cur[(size_t)NB * NT * NO];             // currents [b][t][o]
__device__ __half g_xh[(size_t)2 * NB * NTP * NI];        // x fp16 planes [p][b][t][k]
__device__ __half g_wh[(size_t)2 * NO * NI];              // w fp16 planes [p][n][k]

__device__ __forceinline__ uint32_t smem_u32(const void* p) {
    uint32_t a;
    asm("{ .reg .u64 t; cvta.to.shared.u64 t, %1; cvt.u32.u64 %0, t; }" : "=r"(a) : "l"(p));
    return a;
}

// fp32 -> 2x fp16 split (11+11 mantissa bits)
__device__ __forceinline__ void split2_f16(float v, __half& h0, __half& h1) {
    h0 = __float2half_rn(v);
    float r = __fsub_rn(v, __half2float(h0));
    h1 = __float2half_rn(r);
}

// ---------------------------------------------------------------------------
// wconv: w[k][n] (f32) -> g_wh[p][n][k] (fp16 planes, transposed)
// ---------------------------------------------------------------------------
__global__ __launch_bounds__(256)
void wconv_kernel(const float* __restrict__ w)
{
    __shared__ float tile[32][33];
    const int k0 = blockIdx.x * 32;
    const int n0 = blockIdx.y * 32;
    const int tx = threadIdx.x, ty = threadIdx.y;   // (32, 8)
#pragma unroll
    for (int j = 0; j < 4; j++) {
        int k = k0 + ty + 8 * j;
        tile[ty + 8 * j][tx] = w[(size_t)k * NO + n0 + tx];
    }
    __syncthreads();
#pragma unroll
    for (int j = 0; j < 4; j++) {
        int r = ty + 8 * j;
        int n = n0 + r;
        __half h0, h1;
        split2_f16(tile[tx][r], h0, h1);
        size_t base = (size_t)n * NI + k0 + tx;
        g_wh[base]                   = h0;
        g_wh[(size_t)NO * NI + base] = h1;
    }
}

// ---------------------------------------------------------------------------
// xconv: x[b][k][t] (f32) -> g_xh[p][b][t][k] (fp16 planes, transposed per b)
// ---------------------------------------------------------------------------
__global__ __launch_bounds__(256)
void xconv_kernel(const float* __restrict__ x)
{
    __shared__ float tile[32][33];
    const int b  = blockIdx.z;
    const int k0 = blockIdx.y * 32;
    const int t0 = blockIdx.x * 32;
    const int tx = threadIdx.x, ty = threadIdx.y;   // (32, 8)
    const float* xb = x + (size_t)b * NI * NT;
#pragma unroll
    for (int j = 0; j < 4; j++) {
        int k = k0 + ty + 8 * j;
        int t = t0 + tx;
        tile[ty + 8 * j][tx] = (t < NT) ? xb[(size_t)k * NT + t] : 0.0f;
    }
    __syncthreads();
    const size_t plane = (size_t)NB * NTP * NI;
#pragma unroll
    for (int j = 0; j < 4; j++) {
        int r = ty + 8 * j;
        int t = t0 + r;
        if (t < NT) {
            __half h0, h1;
            split2_f16(tile[tx][r], h0, h1);
            size_t base = ((size_t)b * NTP + t) * NI + k0 + tx;
            g_xh[base]         = h0;
            g_xh[plane + base] = h1;
        }
    }
}

// ---------------------------------------------------------------------------
// GEMM via mma.sync.m16n8k16.f16, fp32-emulated fp16x3.
// FROZEN numerics (verified rel_err==0.0 in R11): main h0x*h0w -> zero-start
// chunk acc per BK=32 (2 k16 MMAs), folded into master with rn add, chunks
// ascending; corr = h0x*h1w + h1x*h0w chained; final cur = main + corr.
// (Zero-start realized as first-MMA-with-zero-C: d = a*b + 0, bit-identical.)
// CTA: 256 thr (8 warps, 2m x 4n), tile 128(t) x 128(o), warp tile 64x32.
// 3-stage cp.async pipeline, ONE __syncthreads per chunk.
// ---------------------------------------------------------------------------
#define PB     16384             // one plane: 128 rows x 64 fp16 (128B rows)
#define BBASE  (2 * PB)          // B planes start within buffer
#define BUFB   (4 * PB)          // [A0][A1][B0][B1] = 64 KB
#define NSTAGE 3
#define SMEMSZ (NSTAGE * BUFB)   // 192 KB
#define NC     16                // 1024 / 64 chunks

__device__ __forceinline__ void ldsm4(uint32_t* r, uint32_t addr) {
    asm volatile("ldmatrix.sync.aligned.m8n8.x4.shared.b16 {%0,%1,%2,%3}, [%4];"
        : "=r"(r[0]), "=r"(r[1]), "=r"(r[2]), "=r"(r[3]) : "r"(addr));
}
__device__ __forceinline__ void mma16816(float* d, const uint32_t* a, uint32_t b0, uint32_t b1) {
    asm volatile("mma.sync.aligned.m16n8k16.row.col.f32.f16.f16.f32 "
        "{%0,%1,%2,%3}, {%4,%5,%6,%7}, {%8,%9}, {%0,%1,%2,%3};"
        : "+f"(d[0]), "+f"(d[1]), "+f"(d[2]), "+f"(d[3])
        : "r"(a[0]), "r"(a[1]), "r"(a[2]), "r"(a[3]), "r"(b0), "r"(b1));
}
// d = a*b + 0  (write-only d; bit-identical to accumulating into zeroed regs)
__device__ __forceinline__ void mma16816_z(float* d, const uint32_t* a, uint32_t b0, uint32_t b1) {
    asm volatile("mma.sync.aligned.m16n8k16.row.col.f32.f16.f16.f32 "
        "{%0,%1,%2,%3}, {%4,%5,%6,%7}, {%8,%9}, {%10,%10,%10,%10};"
        : "=f"(d[0]), "=f"(d[1]), "=f"(d[2]), "=f"(d[3])
        : "r"(a[0]), "r"(a[1]), "r"(a[2]), "r"(a[3]), "r"(b0), "r"(b1), "f"(0.0f));
}

__device__ __forceinline__ void load_chunk(uint32_t sbuf,
                                           const __half* xb, const __half* wb,
                                           int k0, int tid,
                                           size_t xplane, size_t wplane)
{
#pragma unroll
    for (int i = 0; i < 16; i++) {
        int v   = tid + i * 256;          // 0..4095
        int sec = v >> 10;                // 0..3
        int row = (v >> 3) & 127;
        int ch  = v & 7;
        const __half* g;
        if (sec < 2) g = xb + (size_t)(sec)     * xplane + (size_t)row * NI + k0 + ch * 8;
        else         g = wb + (size_t)(sec - 2) * wplane + (size_t)row * NI + k0 + ch * 8;
        uint32_t d = sbuf + sec * PB + row * 128 + ((ch ^ (row & 7)) * 16);
        asm volatile("cp.async.cg.shared.global [%0], [%1], 16;" :: "r"(d), "l"((const void*)g));
    }
}

__global__ __launch_bounds__(256, 1)
void snn_gemm_f16()
{
    extern __shared__ char smem[];
    const int tid  = threadIdx.x;
    const int lane = tid & 31;
    const int wid  = tid >> 5;

    const int b  = blockIdx.z;
    const int t0 = blockIdx.y * 128;
    const int n0 = blockIdx.x * 128;

    const size_t xplane = (size_t)NB * NTP * NI;
    const size_t wplane = (size_t)NO * NI;
    const __half* xb = g_xh + ((size_t)b * NTP + t0) * NI;
    const __half* wb = g_wh + (size_t)n0 * NI;

    const uint32_t sb = smem_u32(smem);

    const int warp_m = (wid >> 2) * 64;    // 0 / 64
    const int warp_n = (wid & 3) * 32;     // 0..96

    const int rA = (lane & 7) + ((lane >> 3) & 1) * 8;
    const int cA = (lane >> 4) & 1;
    const int rB = (lane & 7) + ((lane >> 4) & 1) * 8;
    const int cB = (lane >> 3) & 1;

    float accM[4][4][4], accC[4][4][4], accH[4][4][4];
#pragma unroll
    for (int mt = 0; mt < 4; mt++)
#pragma unroll
        for (int nt = 0; nt < 4; nt++)
#pragma unroll
            for (int q = 0; q < 4; q++) { accM[mt][nt][q] = 0.f; accC[mt][nt][q] = 0.f; }

    // 3-stage prologue: stage 0 and 1 in flight
    load_chunk(sb + 0 * BUFB, xb, wb, 0, tid, xplane, wplane);
    asm volatile("cp.async.commit_group;" ::: "memory");
    load_chunk(sb + 1 * BUFB, xb, wb, 64, tid, xplane, wplane);
    asm volatile("cp.async.commit_group;" ::: "memory");

    int buf = 0;
    for (int c = 0; c < NC; c++) {
        // ensure chunk c's load is complete
        if (c + 1 < NC) {
            asm volatile("cp.async.wait_group 1;" ::: "memory");
        } else {
            asm volatile("cp.async.wait_group 0;" ::: "memory");
        }
        __syncthreads();   // all warps done with the buffer we are about to refill

        // issue load for chunk c+2 into the buffer freed at iteration c-1
        if (c + 2 < NC) {
            int nbuf = buf + 2; if (nbuf >= NSTAGE) nbuf -= NSTAGE;
            load_chunk(sb + nbuf * BUFB, xb, wb, (c + 2) * 64, tid, xplane, wplane);
            asm volatile("cp.async.commit_group;" ::: "memory");
        }

        const uint32_t Ab = sb + buf * BUFB;
        const uint32_t Bb = Ab + BBASE;

        // Two BK=32 halves; accH starts fresh via zero-C first MMA (FROZEN)
#pragma unroll
        for (int half = 0; half < 2; half++) {
#pragma unroll
            for (int kss = 0; kss < 2; kss++) {
                const int ks = half * 2 + kss;
                uint32_t bf[2][2][4];
#pragma unroll
                for (int p = 0; p < 2; p++)
#pragma unroll
                    for (int np = 0; np < 2; np++) {
                        int r  = warp_n + np * 16 + rB;
                        int ch = (ks * 2 + cB) ^ (r & 7);
                        ldsm4(bf[p][np], Bb + p * PB + r * 128 + ch * 16);
                    }
#pragma unroll
                for (int mt = 0; mt < 4; mt++) {
                    int r  = warp_m + mt * 16 + rA;
                    int ch = (ks * 2 + cA) ^ (r & 7);
                    uint32_t a0f[4], a1f[4];
                    ldsm4(a0f, Ab + r * 128 + ch * 16);          // h0 plane
#pragma unroll
                    for (int nt = 0; nt < 4; nt++) {
                        // main: h0x * h0w -> chunk accumulator
                        if (kss == 0)
                            mma16816_z(accH[mt][nt], a0f,
                                       bf[0][nt >> 1][(nt & 1) * 2], bf[0][nt >> 1][(nt & 1) * 2 + 1]);
                        else
                            mma16816(accH[mt][nt], a0f,
                                     bf[0][nt >> 1][(nt & 1) * 2], bf[0][nt >> 1][(nt & 1) * 2 + 1]);
                        // corr: h0x * h1w
                        mma16816(accC[mt][nt], a0f,
                                 bf[1][nt >> 1][(nt & 1) * 2], bf[1][nt >> 1][(nt & 1) * 2 + 1]);
                    }
                    ldsm4(a1f, Ab + PB + r * 128 + ch * 16);     // h1 plane
#pragma unroll
                    for (int nt = 0; nt < 4; nt++) {
                        // corr: h1x * h0w
                        mma16816(accC[mt][nt], a1f,
                                 bf[0][nt >> 1][(nt & 1) * 2], bf[0][nt >> 1][(nt & 1) * 2 + 1]);
                    }
                }
            }

            // fold BK=32 chunk into master (rn add at full magnitude)
#pragma unroll
            for (int mt = 0; mt < 4; mt++)
#pragma unroll
                for (int nt = 0; nt < 4; nt++)
#pragma unroll
                    for (int q = 0; q < 4; q++)
                        accM[mt][nt][q] = __fadd_rn(accM[mt][nt][q], accH[mt][nt][q]);
        }

        buf++; if (buf >= NSTAGE) buf = 0;
    }

    // Epilogue: cur = main + corr
    float* __restrict__ cb = g_cur + (size_t)b * NT * NO;
#pragma unroll
    for (int mt = 0; mt < 4; mt++) {
        int r0 = t0 + warp_m + mt * 16 + (lane >> 2);
#pragma unroll
        for (int nt = 0; nt < 4; nt++) {
            int cc = n0 + warp_n + nt * 8 + (lane & 3) * 2;
            float2 v0, v1;
            v0.x = __fadd_rn(accM[mt][nt][0], accC[mt][nt][0]);
            v0.y = __fadd_rn(accM[mt][nt][1], accC[mt][nt][1]);
            v1.x = __fadd_rn(accM[mt][nt][2], accC[mt][nt][2]);
            v1.y = __fadd_rn(accM[mt][nt][3], accC[mt][nt][3]);
            if (r0 < NT)
                *reinterpret_cast<float2*>(cb + (size_t)r0 * NO + cc) = v0;
            if (r0 + 8 < NT)
                *reinterpret_cast<float2*>(cb + (size_t)(r0 + 8) * NO + cc) = v1;
        }
    }
}

// ---------------------------------------------------------------------------
// Scan: per (b,o) neuron, serial over t (exact reference rounding order).
// ---------------------------------------------------------------------------
#define TT 40   // 1000 % 40 == 0

__global__ __launch_bounds__(128)
void snn_scan_kernel(float* __restrict__ out)
{
    __shared__ float s[128][TT + 1];

    const int b  = blockIdx.y;
    const int o0 = blockIdx.x * 128;
    const int o  = o0 + threadIdx.x;

    const float* __restrict__ cb = g_cur + (size_t)b * NT * NO;
    const float DT = (float)(0.001 / 50.0);

    float v = 0.0f;

    for (int tc = 0; tc < NT; tc += TT) {
#pragma unroll
        for (int tt = 0; tt < TT; tt++) {
            float cur = cb[(size_t)(tc + tt) * NO + o];
            float d  = __fsub_rn(cur, v);
            float dv = __fmul_rn(d, DT);
            v = __fadd_rn(v, dv);
            bool sp = (v >= 1.0f);
            s[threadIdx.x][tt] = sp ? 1.0f : 0.0f;
            v = sp ? 0.0f : v;
        }
        __syncthreads();

        for (int idx = threadIdx.x; idx < 128 * TT; idx += 128) {
            int oo = idx / TT;
            int tt = idx - oo * TT;
            out[((size_t)b * NO + (o0 + oo)) * NT + tc + tt] = s[oo][tt];
        }
        __syncthreads();
    }
}

// ---------------------------------------------------------------------------
extern "C" void kernel_launch(void* const* d_in, const int* in_sizes, int n_in,
                              void* d_out, int out_size)
{
    const float* x = (const float*)d_in[0];   // [32, 1024, 1000]
    const float* w = (const float*)d_in[1];   // [1024, 1024]
    float* out = (float*)d_out;               // [32, 1024, 1000]

    (void)in_sizes; (void)n_in; (void)out_size;

    cudaFuncSetAttribute(snn_gemm_f16, cudaFuncAttributeMaxDynamicSharedMemorySize, SMEMSZ);

    dim3 wgrid(NI / 32, NO / 32);                 // 32 x 32
    wconv_kernel<<<wgrid, dim3(32, 8)>>>(w);

    dim3 xgrid((NT + 31) / 32, NI / 32, NB);      // 32 x 32 x 32
    xconv_kernel<<<xgrid, dim3(32, 8)>>>(x);

    dim3 ggrid(NO / 128, NTP / 128, NB);          // 8 x 8 x 32
    snn_gemm_f16<<<ggrid, 256, SMEMSZ>>>();

    dim3 sgrid(NO / 128, NB);                     // 8 x 32
    snn_scan_kernel<<<sgrid, 128>>>(out);
}

// round 16
// speedup vs baseline: 1.8248x; 1.0244x over previous
#include <cuda_runtime.h>
#include <cuda_fp16.h>
#include <cstdint>

// ---------------------------------------------------------------------------
// Problem shape
#define NB   32      // batch
#define NT   1000    // time steps
#define NO   1024    // n_out
#define NI   1024    // n_in (K)
#define NTP  1024    // padded T

// Scratch (__device__ globals zero-initialized; pad rows stay zero)
__device__ float g_cur[(size_t)NB * NT * NO];             // currents [b][t][o]
__device__ __half g_xh[(size_t)2 * NB * NTP * NI];        // x fp16 planes [p][b][t][k]
__device__ __half g_wh[(size_t)2 * NO * NI];              // w fp16 planes [p][n][k]

__device__ __forceinline__ uint32_t smem_u32(const void* p) {
    uint32_t a;
    asm("{ .reg .u64 t; cvta.to.shared.u64 t, %1; cvt.u32.u64 %0, t; }" : "=r"(a) : "l"(p));
    return a;
}

// fp32 -> 2x fp16 split (11+11 mantissa bits)
__device__ __forceinline__ void split2_f16(float v, __half& h0, __half& h1) {
    h0 = __float2half_rn(v);
    float r = __fsub_rn(v, __half2float(h0));
    h1 = __float2half_rn(r);
}

// ---------------------------------------------------------------------------
// wconv: w[k][n] (f32) -> g_wh[p][n][k] (fp16 planes, transposed)
// ---------------------------------------------------------------------------
__global__ __launch_bounds__(256)
void wconv_kernel(const float* __restrict__ w)
{
    __shared__ float tile[32][33];
    const int k0 = blockIdx.x * 32;
    const int n0 = blockIdx.y * 32;
    const int tx = threadIdx.x, ty = threadIdx.y;   // (32, 8)
#pragma unroll
    for (int j = 0; j < 4; j++) {
        int k = k0 + ty + 8 * j;
        tile[ty + 8 * j][tx] = w[(size_t)k * NO + n0 + tx];
    }
    __syncthreads();
#pragma unroll
    for (int j = 0; j < 4; j++) {
        int r = ty + 8 * j;
        int n = n0 + r;
        __half h0, h1;
        split2_f16(tile[tx][r], h0, h1);
        size_t base = (size_t)n * NI + k0 + tx;
        g_wh[base]                   = h0;
        g_wh[(size_t)NO * NI + base] = h1;
    }
}

// ---------------------------------------------------------------------------
// xconv: x[b][k][t] (f32) -> g_xh[p][b][t][k] (fp16 planes, transposed per b)
// ---------------------------------------------------------------------------
__global__ __launch_bounds__(256)
void xconv_kernel(const float* __restrict__ x)
{
    __shared__ float tile[32][33];
    const int b  = blockIdx.z;
    const int k0 = blockIdx.y * 32;
    const int t0 = blockIdx.x * 32;
    const int tx = threadIdx.x, ty = threadIdx.y;   // (32, 8)
    const float* xb = x + (size_t)b * NI * NT;
#pragma unroll
    for (int j = 0; j < 4; j++) {
        int k = k0 + ty + 8 * j;
        int t = t0 + tx;
        tile[ty + 8 * j][tx] = (t < NT) ? xb[(size_t)k * NT + t] : 0.0f;
    }
    __syncthreads();
    const size_t plane = (size_t)NB * NTP * NI;
#pragma unroll
    for (int j = 0; j < 4; j++) {
        int r = ty + 8 * j;
        int t = t0 + r;
        if (t < NT) {
            __half h0, h1;
            split2_f16(tile[tx][r], h0, h1);
            size_t base = ((size_t)b * NTP + t) * NI + k0 + tx;
            g_xh[base]         = h0;
            g_xh[plane + base] = h1;
        }
    }
}

// ---------------------------------------------------------------------------
// GEMM via mma.sync.m16n8k16.f16, fp32-emulated fp16x3 (EXACT R11 form,
// measured best: 670us total, rel_err==0.0).
// FROZEN numerics: main h0x*h0w -> zero-start chunk acc per BK=32 (2 k16
// MMAs), folded into master with rn add, chunks ascending; corr =
// h0x*h1w + h1x*h0w chained; final cur = main + corr.
// Block 256 thr (8 warps, 2m x 4n), CTA tile 128(t) x 128(o), BK=64 chunks,
// double-buffered cp.async, fold every 2 k16-steps (BK=32 granularity).
// ---------------------------------------------------------------------------
#define PB     16384             // one plane: 128 rows x 64 fp16 (128B rows)
#define BBASE  (2 * PB)          // B planes start within buffer
#define BUFB   (4 * PB)          // [A0][A1][B0][B1] = 64 KB
#define SMEMSZ (2 * BUFB)        // 128 KB
#define NC     16                // 1024 / 64 chunks

__device__ __forceinline__ void ldsm4(uint32_t* r, uint32_t addr) {
    asm volatile("ldmatrix.sync.aligned.m8n8.x4.shared.b16 {%0,%1,%2,%3}, [%4];"
        : "=r"(r[0]), "=r"(r[1]), "=r"(r[2]), "=r"(r[3]) : "r"(addr));
}
__device__ __forceinline__ void mma16816(float* d, const uint32_t* a, uint32_t b0, uint32_t b1) {
    asm volatile("mma.sync.aligned.m16n8k16.row.col.f32.f16.f16.f32 "
        "{%0,%1,%2,%3}, {%4,%5,%6,%7}, {%8,%9}, {%0,%1,%2,%3};"
        : "+f"(d[0]), "+f"(d[1]), "+f"(d[2]), "+f"(d[3])
        : "r"(a[0]), "r"(a[1]), "r"(a[2]), "r"(a[3]), "r"(b0), "r"(b1));
}

__device__ __forceinline__ void load_chunk(uint32_t sbuf,
                                           const __half* xb, const __half* wb,
                                           int k0, int tid,
                                           size_t xplane, size_t wplane)
{
#pragma unroll
    for (int i = 0; i < 16; i++) {
        int v   = tid + i * 256;          // 0..4095
        int sec = v >> 10;                // 0..3
        int row = (v >> 3) & 127;
        int ch  = v & 7;
        const __half* g;
        if (sec < 2) g = xb + (size_t)(sec)     * xplane + (size_t)row * NI + k0 + ch * 8;
        else         g = wb + (size_t)(sec - 2) * wplane + (size_t)row * NI + k0 + ch * 8;
        uint32_t d = sbuf + sec * PB + row * 128 + ((ch ^ (row & 7)) * 16);
        asm volatile("cp.async.cg.shared.global [%0], [%1], 16;" :: "r"(d), "l"((const void*)g));
    }
}

__global__ __launch_bounds__(256, 1)
void snn_gemm_f16()
{
    extern __shared__ char smem[];
    const int tid  = threadIdx.x;
    const int lane = tid & 31;
    const int wid  = tid >> 5;

    const int b  = blockIdx.z;
    const int t0 = blockIdx.y * 128;
    const int n0 = blockIdx.x * 128;

    const size_t xplane = (size_t)NB * NTP * NI;
    const size_t wplane = (size_t)NO * NI;
    const __half* xb = g_xh + ((size_t)b * NTP + t0) * NI;
    const __half* wb = g_wh + (size_t)n0 * NI;

    const uint32_t sb = smem_u32(smem);

    const int warp_m = (wid >> 2) * 64;    // 0 / 64
    const int warp_n = (wid & 3) * 32;     // 0..96

    const int rA = (lane & 7) + ((lane >> 3) & 1) * 8;
    const int cA = (lane >> 4) & 1;
    const int rB = (lane & 7) + ((lane >> 4) & 1) * 8;
    const int cB = (lane >> 3) & 1;

    float accM[4][4][4], accC[4][4][4], accH[4][4][4];
#pragma unroll
    for (int mt = 0; mt < 4; mt++)
#pragma unroll
        for (int nt = 0; nt < 4; nt++)
#pragma unroll
            for (int q = 0; q < 4; q++) { accM[mt][nt][q] = 0.f; accC[mt][nt][q] = 0.f; }

    load_chunk(sb, xb, wb, 0, tid, xplane, wplane);
    asm volatile("cp.async.commit_group;" ::: "memory");

    for (int c = 0; c < NC; c++) {
        if (c + 1 < NC) {
            load_chunk(sb + ((c + 1) & 1) * BUFB, xb, wb, (c + 1) * 64, tid, xplane, wplane);
            asm volatile("cp.async.commit_group;" ::: "memory");
            asm volatile("cp.async.wait_group 1;" ::: "memory");
        } else {
            asm volatile("cp.async.wait_group 0;" ::: "memory");
        }
        __syncthreads();

        const uint32_t Ab = sb + (c & 1) * BUFB;
        const uint32_t Bb = Ab + BBASE;

        // Two BK=32 halves per chunk; fresh chunk accumulator each half (FROZEN)
#pragma unroll
        for (int half = 0; half < 2; half++) {
#pragma unroll
            for (int mt = 0; mt < 4; mt++)
#pragma unroll
                for (int nt = 0; nt < 4; nt++)
#pragma unroll
                    for (int q = 0; q < 4; q++) accH[mt][nt][q] = 0.f;

#pragma unroll
            for (int kss = 0; kss < 2; kss++) {
                const int ks = half * 2 + kss;
                // B fragments: 2 planes x 2 n16-groups
                uint32_t bf[2][2][4];
#pragma unroll
                for (int p = 0; p < 2; p++)
#pragma unroll
                    for (int np = 0; np < 2; np++) {
                        int r  = warp_n + np * 16 + rB;
                        int ch = (ks * 2 + cB) ^ (r & 7);
                        ldsm4(bf[p][np], Bb + p * PB + r * 128 + ch * 16);
                    }
#pragma unroll
                for (int mt = 0; mt < 4; mt++) {
                    int r  = warp_m + mt * 16 + rA;
                    int ch = (ks * 2 + cA) ^ (r & 7);
                    uint32_t a0f[4], a1f[4];
                    ldsm4(a0f, Ab + r * 128 + ch * 16);          // h0 plane
#pragma unroll
                    for (int nt = 0; nt < 4; nt++) {
                        // main: h0x * h0w -> chunk accumulator
                        mma16816(accH[mt][nt], a0f,
                                 bf[0][nt >> 1][(nt & 1) * 2], bf[0][nt >> 1][(nt & 1) * 2 + 1]);
                        // corr: h0x * h1w
                        mma16816(accC[mt][nt], a0f,
                                 bf[1][nt >> 1][(nt & 1) * 2], bf[1][nt >> 1][(nt & 1) * 2 + 1]);
                    }
                    ldsm4(a1f, Ab + PB + r * 128 + ch * 16);     // h1 plane
#pragma unroll
                    for (int nt = 0; nt < 4; nt++) {
                        // corr: h1x * h0w
                        mma16816(accC[mt][nt], a1f,
                                 bf[0][nt >> 1][(nt & 1) * 2], bf[0][nt >> 1][(nt & 1) * 2 + 1]);
                    }
                }
            }

            // fold BK=32 chunk into master (rn add at full magnitude)
#pragma unroll
            for (int mt = 0; mt < 4; mt++)
#pragma unroll
                for (int nt = 0; nt < 4; nt++)
#pragma unroll
                    for (int q = 0; q < 4; q++)
                        accM[mt][nt][q] = __fadd_rn(accM[mt][nt][q], accH[mt][nt][q]);
        }
        __syncthreads();
    }

    // Epilogue: cur = main + corr
    float* __restrict__ cb = g_cur + (size_t)b * NT * NO;
#pragma unroll
    for (int mt = 0; mt < 4; mt++) {
        int r0 = t0 + warp_m + mt * 16 + (lane >> 2);
#pragma unroll
        for (int nt = 0; nt < 4; nt++) {
            int cc = n0 + warp_n + nt * 8 + (lane & 3) * 2;
            float2 v0, v1;
            v0.x = __fadd_rn(accM[mt][nt][0], accC[mt][nt][0]);
            v0.y = __fadd_rn(accM[mt][nt][1], accC[mt][nt][1]);
            v1.x = __fadd_rn(accM[mt][nt][2], accC[mt][nt][2]);
            v1.y = __fadd_rn(accM[mt][nt][3], accC[mt][nt][3]);
            if (r0 < NT)
                *reinterpret_cast<float2*>(cb + (size_t)r0 * NO + cc) = v0;
            if (r0 + 8 < NT)
                *reinterpret_cast<float2*>(cb + (size_t)(r0 + 8) * NO + cc) = v1;
        }
    }
}

// ---------------------------------------------------------------------------
// Scan: per (b,o) neuron, serial over t (exact reference rounding order).
// MLP fix: load all TT currents into registers FIRST (40 independent loads
// in flight), then run the serial v-chain from registers. Arithmetic
// unchanged.
// ---------------------------------------------------------------------------
#define TT 40   // 1000 % 40 == 0

__global__ __launch_bounds__(128)
void snn_scan_kernel(float* __restrict__ out)
{
    __shared__ float s[128][TT + 1];

    const int b  = blockIdx.y;
    const int o0 = blockIdx.x * 128;
    const int o  = o0 + threadIdx.x;

    const float* __restrict__ cb = g_cur + (size_t)b * NT * NO;
    const float DT = (float)(0.001 / 50.0);

    float v = 0.0f;
    float rc[TT];

    for (int tc = 0; tc < NT; tc += TT) {
        // Phase 1: issue all TT loads (independent -> MLP = TT)
#pragma unroll
        for (int tt = 0; tt < TT; tt++)
            rc[tt] = cb[(size_t)(tc + tt) * NO + o];

        // Phase 2: serial v-chain from registers (exact reference rounding)
#pragma unroll
        for (int tt = 0; tt < TT; tt++) {
            float d  = __fsub_rn(rc[tt], v);
            float dv = __fmul_rn(d, DT);
            v = __fadd_rn(v, dv);
            bool sp = (v >= 1.0f);
            s[threadIdx.x][tt] = sp ? 1.0f : 0.0f;
            v = sp ? 0.0f : v;
        }
        __syncthreads();

        // Transposed, coalesced-along-t store
        for (int idx = threadIdx.x; idx < 128 * TT; idx += 128) {
            int oo = idx / TT;
            int tt = idx - oo * TT;
            out[((size_t)b * NO + (o0 + oo)) * NT + tc + tt] = s[oo][tt];
        }
        __syncthreads();
    }
}

// ---------------------------------------------------------------------------
extern "C" void kernel_launch(void* const* d_in, const int* in_sizes, int n_in,
                              void* d_out, int out_size)
{
    const float* x = (const float*)d_in[0];   // [32, 1024, 1000]
    const float* w = (const float*)d_in[1];   // [1024, 1024]
    float* out = (float*)d_out;               // [32, 1024, 1000]

    (void)in_sizes; (void)n_in; (void)out_size;

    cudaFuncSetAttribute(snn_gemm_f16, cudaFuncAttributeMaxDynamicSharedMemorySize, SMEMSZ);

    dim3 wgrid(NI / 32, NO / 32);                 // 32 x 32
    wconv_kernel<<<wgrid, dim3(32, 8)>>>(w);

    dim3 xgrid((NT + 31) / 32, NI / 32, NB);      // 32 x 32 x 32
    xconv_kernel<<<xgrid, dim3(32, 8)>>>(x);

    dim3 ggrid(NO / 128, NTP / 128, NB);          // 8 x 8 x 32
    snn_gemm_f16<<<ggrid, 256, SMEMSZ>>>();

    dim3 sgrid(NO / 128, NB);                     // 8 x 32
    snn_scan_kernel<<<sgrid, 128>>>(out);
}

// round 17
// speedup vs baseline: 2.0158x; 1.1047x over previous
#include <cuda_runtime.h>
#include <cuda_fp16.h>
#include <cstdint>

// ---------------------------------------------------------------------------
// Problem shape
#define NB   32      // batch
#define NT   1000    // time steps
#define NO   1024    // n_out
#define NI   1024    // n_in (K)
#define NTP  1024    // padded T

// Scratch (__device__ globals zero-initialized; pad rows stay zero)
__device__ float g_cur[(size_t)NB * NT * NO];             // currents [b][t][o]
__device__ __half g_xh[(size_t)2 * NB * NTP * NI];        // x fp16 planes [p][b][t][k]
__device__ __half g_wh[(size_t)2 * NO * NI];              // w fp16 planes [p][n][k]

__device__ __forceinline__ uint32_t smem_u32(const void* p) {
    uint32_t a;
    asm("{ .reg .u64 t; cvta.to.shared.u64 t, %1; cvt.u32.u64 %0, t; }" : "=r"(a) : "l"(p));
    return a;
}

// fp32 -> 2x fp16 split (11+11 mantissa bits)
__device__ __forceinline__ void split2_f16(float v, __half& h0, __half& h1) {
    h0 = __float2half_rn(v);
    float r = __fsub_rn(v, __half2float(h0));
    h1 = __float2half_rn(r);
}

// ---------------------------------------------------------------------------
// wconv: w[k][n] (f32) -> g_wh[p][n][k] (fp16 planes, transposed)
// ---------------------------------------------------------------------------
__global__ __launch_bounds__(256)
void wconv_kernel(const float* __restrict__ w)
{
    __shared__ float tile[32][33];
    const int k0 = blockIdx.x * 32;
    const int n0 = blockIdx.y * 32;
    const int tx = threadIdx.x, ty = threadIdx.y;   // (32, 8)
#pragma unroll
    for (int j = 0; j < 4; j++) {
        int k = k0 + ty + 8 * j;
        tile[ty + 8 * j][tx] = w[(size_t)k * NO + n0 + tx];
    }
    __syncthreads();
#pragma unroll
    for (int j = 0; j < 4; j++) {
        int r = ty + 8 * j;
        int n = n0 + r;
        __half h0, h1;
        split2_f16(tile[tx][r], h0, h1);
        size_t base = (size_t)n * NI + k0 + tx;
        g_wh[base]                   = h0;
        g_wh[(size_t)NO * NI + base] = h1;
    }
}

// ---------------------------------------------------------------------------
// xconv: x[b][k][t] (f32) -> g_xh[p][b][t][k] (fp16 planes, transposed per b)
// K-tile 64 wide; each thread stores __half2 k-pairs (4B coalesced stores).
// ---------------------------------------------------------------------------
__global__ __launch_bounds__(256)
void xconv_kernel(const float* __restrict__ x)
{
    __shared__ float tile[64][33];
    const int b  = blockIdx.z;
    const int k0 = blockIdx.y * 64;
    const int t0 = blockIdx.x * 32;
    const int tx = threadIdx.x, ty = threadIdx.y;   // (32, 8)
    const float* xb = x + (size_t)b * NI * NT;
    const int t = t0 + tx;
#pragma unroll
    for (int j = 0; j < 8; j++) {
        int k = k0 + ty + 8 * j;
        tile[ty + 8 * j][tx] = (t < NT) ? xb[(size_t)k * NT + t] : 0.0f;
    }
    __syncthreads();
    const size_t plane = (size_t)NB * NTP * NI;
#pragma unroll
    for (int j = 0; j < 4; j++) {
        int r  = ty + 8 * j;          // t-local 0..31
        int tt = t0 + r;
        if (tt < NT) {
            float va = tile[2 * tx][r];
            float vb = tile[2 * tx + 1][r];
            __half a0, a1, b0, b1;
            split2_f16(va, a0, a1);
            split2_f16(vb, b0, b1);
            size_t base = ((size_t)b * NTP + tt) * NI + k0 + 2 * tx;
            *reinterpret_cast<__half2*>(&g_xh[base]) = __halves2half2(a0, b0);
            *reinterpret_cast<__half2*>(&g_xh[plane + base]) = __halves2half2(a1, b1);
        }
    }
}

// ---------------------------------------------------------------------------
// GEMM via mma.sync.m16n8k16.f16, fp32-emulated fp16x3 (EXACT R11 form,
// measured best, rel_err==0.0). FROZEN numerics: main h0x*h0w -> zero-start
// chunk acc per BK=32 (2 k16 MMAs), folded into master with rn add, chunks
// ascending; corr = h0x*h1w + h1x*h0w chained; final cur = main + corr.
// Block 256 thr (8 warps, 2m x 4n), CTA tile 128(t) x 128(o), BK=64 chunks,
// double-buffered cp.async, fold every 2 k16-steps (BK=32 granularity).
// ---------------------------------------------------------------------------
#define PB     16384             // one plane: 128 rows x 64 fp16 (128B rows)
#define BBASE  (2 * PB)          // B planes start within buffer
#define BUFB   (4 * PB)          // [A0][A1][B0][B1] = 64 KB
#define SMEMSZ (2 * BUFB)        // 128 KB
#define NC     16                // 1024 / 64 chunks

__device__ __forceinline__ void ldsm4(uint32_t* r, uint32_t addr) {
    asm volatile("ldmatrix.sync.aligned.m8n8.x4.shared.b16 {%0,%1,%2,%3}, [%4];"
        : "=r"(r[0]), "=r"(r[1]), "=r"(r[2]), "=r"(r[3]) : "r"(addr));
}
__device__ __forceinline__ void mma16816(float* d, const uint32_t* a, uint32_t b0, uint32_t b1) {
    asm volatile("mma.sync.aligned.m16n8k16.row.col.f32.f16.f16.f32 "
        "{%0,%1,%2,%3}, {%4,%5,%6,%7}, {%8,%9}, {%0,%1,%2,%3};"
        : "+f"(d[0]), "+f"(d[1]), "+f"(d[2]), "+f"(d[3])
        : "r"(a[0]), "r"(a[1]), "r"(a[2]), "r"(a[3]), "r"(b0), "r"(b1));
}

__device__ __forceinline__ void load_chunk(uint32_t sbuf,
                                           const __half* xb, const __half* wb,
                                           int k0, int tid,
                                           size_t xplane, size_t wplane)
{
#pragma unroll
    for (int i = 0; i < 16; i++) {
        int v   = tid + i * 256;          // 0..4095
        int sec = v >> 10;                // 0..3
        int row = (v >> 3) & 127;
        int ch  = v & 7;
        const __half* g;
        if (sec < 2) g = xb + (size_t)(sec)     * xplane + (size_t)row * NI + k0 + ch * 8;
        else         g = wb + (size_t)(sec - 2) * wplane + (size_t)row * NI + k0 + ch * 8;
        uint32_t d = sbuf + sec * PB + row * 128 + ((ch ^ (row & 7)) * 16);
        asm volatile("cp.async.cg.shared.global [%0], [%1], 16;" :: "r"(d), "l"((const void*)g));
    }
}

__global__ __launch_bounds__(256, 1)
void snn_gemm_f16()
{
    extern __shared__ char smem[];
    const int tid  = threadIdx.x;
    const int lane = tid & 31;
    const int wid  = tid >> 5;

    const int b  = blockIdx.z;
    const int t0 = blockIdx.y * 128;
    const int n0 = blockIdx.x * 128;

    const size_t xplane = (size_t)NB * NTP * NI;
    const size_t wplane = (size_t)NO * NI;
    const __half* xb = g_xh + ((size_t)b * NTP + t0) * NI;
    const __half* wb = g_wh + (size_t)n0 * NI;

    const uint32_t sb = smem_u32(smem);

    const int warp_m = (wid >> 2) * 64;    // 0 / 64
    const int warp_n = (wid & 3) * 32;     // 0..96

    const int rA = (lane & 7) + ((lane >> 3) & 1) * 8;
    const int cA = (lane >> 4) & 1;
    const int rB = (lane & 7) + ((lane >> 4) & 1) * 8;
    const int cB = (lane >> 3) & 1;

    float accM[4][4][4], accC[4][4][4], accH[4][4][4];
#pragma unroll
    for (int mt = 0; mt < 4; mt++)
#pragma unroll
        for (int nt = 0; nt < 4; nt++)
#pragma unroll
            for (int q = 0; q < 4; q++) { accM[mt][nt][q] = 0.f; accC[mt][nt][q] = 0.f; }

    load_chunk(sb, xb, wb, 0, tid, xplane, wplane);
    asm volatile("cp.async.commit_group;" ::: "memory");

    for (int c = 0; c < NC; c++) {
        if (c + 1 < NC) {
            load_chunk(sb + ((c + 1) & 1) * BUFB, xb, wb, (c + 1) * 64, tid, xplane, wplane);
            asm volatile("cp.async.commit_group;" ::: "memory");
            asm volatile("cp.async.wait_group 1;" ::: "memory");
        } else {
            asm volatile("cp.async.wait_group 0;" ::: "memory");
        }
        __syncthreads();

        const uint32_t Ab = sb + (c & 1) * BUFB;
        const uint32_t Bb = Ab + BBASE;

        // Two BK=32 halves per chunk; fresh chunk accumulator each half (FROZEN)
#pragma unroll
        for (int half = 0; half < 2; half++) {
#pragma unroll
            for (int mt = 0; mt < 4; mt++)
#pragma unroll
                for (int nt = 0; nt < 4; nt++)
#pragma unroll
                    for (int q = 0; q < 4; q++) accH[mt][nt][q] = 0.f;

#pragma unroll
            for (int kss = 0; kss < 2; kss++) {
                const int ks = half * 2 + kss;
                uint32_t bf[2][2][4];
#pragma unroll
                for (int p = 0; p < 2; p++)
#pragma unroll
                    for (int np = 0; np < 2; np++) {
                        int r  = warp_n + np * 16 + rB;
                        int ch = (ks * 2 + cB) ^ (r & 7);
                        ldsm4(bf[p][np], Bb + p * PB + r * 128 + ch * 16);
                    }
#pragma unroll
                for (int mt = 0; mt < 4; mt++) {
                    int r  = warp_m + mt * 16 + rA;
                    int ch = (ks * 2 + cA) ^ (r & 7);
                    uint32_t a0f[4], a1f[4];
                    ldsm4(a0f, Ab + r * 128 + ch * 16);          // h0 plane
#pragma unroll
                    for (int nt = 0; nt < 4; nt++) {
                        mma16816(accH[mt][nt], a0f,
                                 bf[0][nt >> 1][(nt & 1) * 2], bf[0][nt >> 1][(nt & 1) * 2 + 1]);
                        mma16816(accC[mt][nt], a0f,
                                 bf[1][nt >> 1][(nt & 1) * 2], bf[1][nt >> 1][(nt & 1) * 2 + 1]);
                    }
                    ldsm4(a1f, Ab + PB + r * 128 + ch * 16);     // h1 plane
#pragma unroll
                    for (int nt = 0; nt < 4; nt++) {
                        mma16816(accC[mt][nt], a1f,
                                 bf[0][nt >> 1][(nt & 1) * 2], bf[0][nt >> 1][(nt & 1) * 2 + 1]);
                    }
                }
            }

            // fold BK=32 chunk into master (rn add at full magnitude)
#pragma unroll
            for (int mt = 0; mt < 4; mt++)
#pragma unroll
                for (int nt = 0; nt < 4; nt++)
#pragma unroll
                    for (int q = 0; q < 4; q++)
                        accM[mt][nt][q] = __fadd_rn(accM[mt][nt][q], accH[mt][nt][q]);
        }
        __syncthreads();
    }

    // Epilogue: cur = main + corr
    float* __restrict__ cb = g_cur + (size_t)b * NT * NO;
#pragma unroll
    for (int mt = 0; mt < 4; mt++) {
        int r0 = t0 + warp_m + mt * 16 + (lane >> 2);
#pragma unroll
        for (int nt = 0; nt < 4; nt++) {
            int cc = n0 + warp_n + nt * 8 + (lane & 3) * 2;
            float2 v0, v1;
            v0.x = __fadd_rn(accM[mt][nt][0], accC[mt][nt][0]);
            v0.y = __fadd_rn(accM[mt][nt][1], accC[mt][nt][1]);
            v1.x = __fadd_rn(accM[mt][nt][2], accC[mt][nt][2]);
            v1.y = __fadd_rn(accM[mt][nt][3], accC[mt][nt][3]);
            if (r0 < NT)
                *reinterpret_cast<float2*>(cb + (size_t)r0 * NO + cc) = v0;
            if (r0 + 8 < NT)
                *reinterpret_cast<float2*>(cb + (size_t)(r0 + 8) * NO + cc) = v1;
        }
    }
}

// ---------------------------------------------------------------------------
// Scan: per (b,o) neuron, serial over t (exact reference rounding order).
// cp.async double-buffered input staging: tile [TT t][128 o] loaded with
// 16B async copies (latency overlapped with previous tile's chain), then
// the serial v-chain reads smem; spikes staged in [o][t] smem and written
// out as float4 (16B-aligned since NT*4 = 4000 % 16 == 0).
// ---------------------------------------------------------------------------
#define TT    40                  // 1000 % 40 == 0; 25 tiles
#define TROW  132                 // tile row stride in floats (128 + 4 pad)
#define TILEF (TT * TROW)         // floats per tile buffer
#define SCAN_SMEM ((2 * TILEF + 128 * TT) * 4)   // 62720 bytes

__global__ __launch_bounds__(128)
void snn_scan_kernel(float* __restrict__ out)
{
    extern __shared__ float sm[];
    float* tiles = sm;                 // 2 tile buffers
    float* sbuf  = sm + 2 * TILEF;     // spikes [128 o][TT t]

    const int b   = blockIdx.y;
    const int o0  = blockIdx.x * 128;
    const int tid = threadIdx.x;

    const float* __restrict__ cb = g_cur + (size_t)b * NT * NO;
    const float DT = (float)(0.001 / 50.0);
    const uint32_t smb = smem_u32(sm);

    // issue tile 0
    {
        uint32_t dstb = smb;
#pragma unroll
        for (int i = 0; i < 10; i++) {
            int f4  = tid + i * 128;          // 0..1279
            int tr  = f4 >> 5;
            int tc4 = f4 & 31;
            const float* g = cb + (size_t)tr * NO + o0 + tc4 * 4;
            uint32_t d = dstb + tr * (TROW * 4) + tc4 * 16;
            asm volatile("cp.async.cg.shared.global [%0], [%1], 16;" :: "r"(d), "l"((const void*)g));
        }
        asm volatile("cp.async.commit_group;" ::: "memory");
    }

    float v = 0.0f;

    for (int ti = 0; ti < 25; ti++) {
        const int tc = ti * TT;

        // issue next tile into the other buffer (freed by last iter's sync)
        if (ti + 1 < 25) {
            uint32_t dstb = smb + ((ti + 1) & 1) * (TILEF * 4);
#pragma unroll
            for (int i = 0; i < 10; i++) {
                int f4  = tid + i * 128;
                int tr  = f4 >> 5;
                int tc4 = f4 & 31;
                const float* g = cb + (size_t)(tc + TT + tr) * NO + o0 + tc4 * 4;
                uint32_t d = dstb + tr * (TROW * 4) + tc4 * 16;
                asm volatile("cp.async.cg.shared.global [%0], [%1], 16;" :: "r"(d), "l"((const void*)g));
            }
            asm volatile("cp.async.commit_group;" ::: "memory");
            asm volatile("cp.async.wait_group 1;" ::: "memory");
        } else {
            asm volatile("cp.async.wait_group 0;" ::: "memory");
        }
        __syncthreads();   // tile ti visible to all threads

        // serial v-chain from smem (exact reference rounding order)
        const float* tbuf = tiles + (ti & 1) * TILEF;
#pragma unroll
        for (int tt = 0; tt < TT; tt++) {
            float cur = tbuf[tt * TROW + tid];
            float d  = __fsub_rn(cur, v);
            float dv = __fmul_rn(d, DT);
            v = __fadd_rn(v, dv);
            bool sp = (v >= 1.0f);
            sbuf[tid * TT + tt] = sp ? 1.0f : 0.0f;
            v = sp ? 0.0f : v;
        }
        __syncthreads();   // sbuf ready

        // float4 transposed store: out[b][o][tc..tc+TT)
#pragma unroll
        for (int i = 0; i < 10; i++) {
            int f4 = tid + i * 128;           // 0..1279
            int oo = f4 / 10;
            int t4 = f4 - oo * 10;
            float4 val = *reinterpret_cast<const float4*>(&sbuf[oo * TT + t4 * 4]);
            *reinterpret_cast<float4*>(
                out + ((size_t)b * NO + o0 + oo) * NT + tc + t4 * 4) = val;
        }
        __syncthreads();   // sbuf & tile buffer reusable
    }
}

// ---------------------------------------------------------------------------
extern "C" void kernel_launch(void* const* d_in, const int* in_sizes, int n_in,
                              void* d_out, int out_size)
{
    const float* x = (const float*)d_in[0];   // [32, 1024, 1000]
    const float* w = (const float*)d_in[1];   // [1024, 1024]
    float* out = (float*)d_out;               // [32, 1024, 1000]

    (void)in_sizes; (void)n_in; (void)out_size;

    cudaFuncSetAttribute(snn_gemm_f16, cudaFuncAttributeMaxDynamicSharedMemorySize, SMEMSZ);
    cudaFuncSetAttribute(snn_scan_kernel, cudaFuncAttributeMaxDynamicSharedMemorySize, SCAN_SMEM);

    dim3 wgrid(NI / 32, NO / 32);                 // 32 x 32
    wconv_kernel<<<wgrid, dim3(32, 8)>>>(w);

    dim3 xgrid((NT + 31) / 32, NI / 64, NB);      // 32 x 16 x 32
    xconv_kernel<<<xgrid, dim3(32, 8)>>>(x);

    dim3 ggrid(NO / 128, NTP / 128, NB);          // 8 x 8 x 32
    snn_gemm_f16<<<ggrid, 256, SMEMSZ>>>();

    dim3 sgrid(NO / 128, NB);                     // 8 x 32
    snn_scan_kernel<<<sgrid, 128, SCAN_SMEM>>>(out);
}